// round 1
// baseline (speedup 1.0000x reference)
#include <cuda_runtime.h>

// ---------------------------------------------------------------------------
// WaveNet vocoder, fp32, FFMA2 (fma.rn.f32x2) tiled GEMMs.
// B=2, T=8192, RES_C=512, SKIP_C=256, MEL_C=80, K=3, 30 layers.
// ---------------------------------------------------------------------------

#define T_LEN 8192
#define NB    2
#define RC    512
#define SC    256
#define NL    30

// Scratch (static device globals; no allocation allowed).
__device__ float g_Wp [NL*3*RC*1024];   // [layer][tap][ci][co(1024: f then g)]
__device__ float g_RSp[NL*RC*768];      // [layer][ci][m(768: 512 res co, 256 skip co)]
__device__ float g_F1p[SC*SC];          // [ci][co]
__device__ float g_x   [NB*RC*T_LEN];
__device__ float g_a   [NB*RC*T_LEN];
__device__ float g_skip[NB*SC*T_LEN];
__device__ float g_y   [NB*SC*T_LEN];

// ---- packed fp32x2 helpers -------------------------------------------------
__device__ __forceinline__ void ffma2(unsigned long long& d, unsigned long long a,
                                      unsigned long long b) {
    asm("fma.rn.f32x2 %0, %1, %2, %0;" : "+l"(d) : "l"(a), "l"(b));
}
__device__ __forceinline__ unsigned long long pack2(float v) {
    unsigned long long r; unsigned u = __float_as_uint(v);
    asm("mov.b64 %0, {%1, %1};" : "=l"(r) : "r"(u));
    return r;
}
__device__ __forceinline__ float lo2(unsigned long long v) {
    return __uint_as_float((unsigned)v);
}
__device__ __forceinline__ float hi2(unsigned long long v) {
    return __uint_as_float((unsigned)(v >> 32));
}

__device__ __forceinline__ float gatefn(float f, float g) {
    // tanh(f) * sigmoid(g) via fast exp / fast div (MUFU). inf-safe.
    float ef = __expf(2.f * f);
    float th = 1.f - __fdividef(2.f, ef + 1.f);
    float sg = __fdividef(1.f, 1.f + __expf(-g));
    return th * sg;
}

// ---- weight prep (run every call; deterministic) --------------------------
__global__ void prep_dil_k(const float* __restrict__ dil_w) {
    int idx = blockIdx.x * 256 + threadIdx.x;           // 47,185,920 total
    int co = idx & 1023;
    int r  = idx >> 10;
    int ci = r & 511; r >>= 9;
    int k  = r % 3;
    int l  = r / 3;
    g_Wp[idx] = dil_w[((l * 1024 + co) * 512 + ci) * 3 + k];
}

__global__ void prep_rs_k(const float* __restrict__ res_w,
                          const float* __restrict__ skip_w) {
    int idx = blockIdx.x * 256 + threadIdx.x;           // 11,796,480 total
    int m  = idx % 768;
    int r  = idx / 768;
    int ci = r & 511;
    int l  = r >> 9;
    float v;
    if (m < 512) v = res_w [(l * 512 + m)        * 512 + ci];
    else         v = skip_w[(l * 256 + (m - 512)) * 512 + ci];
    g_RSp[idx] = v;
}

__global__ void prep_fc1_k(const float* __restrict__ fc1_w) {
    int idx = blockIdx.x * 256 + threadIdx.x;           // 65536
    int co = idx & 255, ci = idx >> 8;
    g_F1p[ci * 256 + co] = fc1_w[co * 256 + ci];
}

__global__ void zero_skip_k() {
    int idx = blockIdx.x * 256 + threadIdx.x;
    g_skip[idx] = 0.f;
}

// ---- init: x = start conv(audio) + mel 1x1 conv ---------------------------
__global__ __launch_bounds__(256) void init_x_k(
        const float* __restrict__ mel, const float* __restrict__ audio,
        const float* __restrict__ start_w, const float* __restrict__ start_b,
        const float* __restrict__ mel_w, const float* __restrict__ mel_b) {
    __shared__ float mels[80][128];
    __shared__ float auds[128];
    const int tid = threadIdx.x;
    const int t0 = blockIdx.x * 128, b = blockIdx.y, c0 = blockIdx.z * 64;
    for (int idx = tid; idx < 80 * 128; idx += 256) {
        int m = idx / 128, cl = idx % 128;
        mels[m][cl] = mel[((size_t)(b * 80 + m)) * T_LEN + t0 + cl];
    }
    if (tid < 128) auds[tid] = audio[(size_t)b * T_LEN + t0 + tid];
    __syncthreads();
    const int txx = tid & 31, cy = tid >> 5;
    #pragma unroll
    for (int r2 = 0; r2 < 8; r2++) {
        int c = c0 + cy * 8 + r2;
        float a0 = 0.f, a1 = 0.f, a2 = 0.f, a3 = 0.f;
        const float* wr = mel_w + (size_t)c * 80;
        for (int m = 0; m < 80; m++) {
            float w = __ldg(&wr[m]);                    // warp-uniform, L1 hit
            a0 += w * mels[m][txx];
            a1 += w * mels[m][txx + 32];
            a2 += w * mels[m][txx + 64];
            a3 += w * mels[m][txx + 96];
        }
        float sw = start_w[c], bb = start_b[c] + mel_b[c];
        float* row = g_x + ((size_t)(b * 512 + c)) * T_LEN + t0;
        row[txx]      = a0 + sw * auds[txx]      + bb;
        row[txx + 32] = a1 + sw * auds[txx + 32] + bb;
        row[txx + 64] = a2 + sw * auds[txx + 64] + bb;
        row[txx + 96] = a3 + sw * auds[txx + 96] + bb;
    }
}

// ---------------------------------------------------------------------------
// Dilated conv + gate. Block tile: 128 rows (64 f-ch + paired 64 g-ch) x 128 t.
// K = 512 ci x 3 taps. Register-prefetch pipelined single smem buffer.
// Thread (tx=tid&15, ty=tid>>4): rows {ty*4..+3 (f), 64+ty*4..+3 (g)},
// cols {tx*4..+3} and {64+tx*4..+3}; accumulators packed f32x2 along t.
// ---------------------------------------------------------------------------
__global__ __launch_bounds__(256) void dil_gate_k(
        const float* __restrict__ dil_b, int layer, int dil) {
    __shared__ __align__(16) float Ws[16][128];
    __shared__ __align__(16) float Xs[16][128];
    const int tid = threadIdx.x, tx = tid & 15, ty = tid >> 4;
    const int t0 = blockIdx.x * 128, b = blockIdx.y, c0 = blockIdx.z * 64;
    const float* __restrict__ wl = g_Wp + (size_t)layer * (3 * 512 * 1024);
    const float* __restrict__ xb = g_x + (size_t)b * (RC * T_LEN);

    unsigned long long acc[8][4];
    #pragma unroll
    for (int i = 0; i < 8; i++)
        #pragma unroll
        for (int j = 0; j < 4; j++) acc[i][j] = 0ull;

    float pw[8], px[8];
    {   // prefetch (tap=0, kc=0)
        int shift = -dil;
        #pragma unroll
        for (int l = 0; l < 8; l++) {
            int idx = tid + l * 256, r = idx >> 7, m = idx & 127;
            int co = (m < 64) ? (c0 + m) : (512 + c0 + m - 64);
            pw[l] = wl[r * 1024 + co];
            int ts = t0 + m + shift;
            px[l] = (ts >= 0 && ts < T_LEN) ? xb[r * T_LEN + ts] : 0.f;
        }
    }
    for (int it = 0; it < 96; ++it) {
        #pragma unroll
        for (int l = 0; l < 8; l++) {
            int idx = tid + l * 256, r = idx >> 7, m = idx & 127;
            Ws[r][m] = pw[l];
            Xs[r][m] = px[l];
        }
        __syncthreads();
        if (it + 1 < 96) {          // issue next tile's LDGs; overlap compute
            int tap = (it + 1) >> 5, kc = ((it + 1) & 31) * 16;
            int shift = (tap - 1) * dil;
            #pragma unroll
            for (int l = 0; l < 8; l++) {
                int idx = tid + l * 256, r = idx >> 7, m = idx & 127;
                int co = (m < 64) ? (c0 + m) : (512 + c0 + m - 64);
                pw[l] = wl[(tap * 512 + kc + r) * 1024 + co];
                int ts = t0 + m + shift;
                px[l] = (ts >= 0 && ts < T_LEN) ? xb[(kc + r) * T_LEN + ts] : 0.f;
            }
        }
        #pragma unroll
        for (int k = 0; k < 16; k++) {
            const float4 wa = *(const float4*)&Ws[k][ty * 4];
            const float4 wb = *(const float4*)&Ws[k][64 + ty * 4];
            const ulonglong2 xA = *(const ulonglong2*)&Xs[k][tx * 4];
            const ulonglong2 xB = *(const ulonglong2*)&Xs[k][64 + tx * 4];
            unsigned long long xf[4] = {xA.x, xA.y, xB.x, xB.y};
            float wv[8] = {wa.x, wa.y, wa.z, wa.w, wb.x, wb.y, wb.z, wb.w};
            #pragma unroll
            for (int i = 0; i < 8; i++) {
                unsigned long long wp = pack2(wv[i]);
                #pragma unroll
                for (int j = 0; j < 4; j++) ffma2(acc[i][j], wp, xf[j]);
            }
        }
        __syncthreads();
    }
    // epilogue: bias + gated activation -> g_a
    float* __restrict__ ab = g_a + (size_t)b * (RC * T_LEN);
    #pragma unroll
    for (int i = 0; i < 4; i++) {
        int c = c0 + ty * 4 + i;
        float bf = dil_b[layer * 1024 + c];
        float bg = dil_b[layer * 1024 + 512 + c];
        float o[8];
        #pragma unroll
        for (int j = 0; j < 4; j++) {
            float fl = lo2(acc[i][j]) + bf,     fh = hi2(acc[i][j]) + bf;
            float gl = lo2(acc[4 + i][j]) + bg, gh = hi2(acc[4 + i][j]) + bg;
            o[2 * j]     = gatefn(fl, gl);
            o[2 * j + 1] = gatefn(fh, gh);
        }
        float* row = ab + (size_t)c * T_LEN + t0;
        *(float4*)&row[tx * 4]      = make_float4(o[0], o[1], o[2], o[3]);
        *(float4*)&row[64 + tx * 4] = make_float4(o[4], o[5], o[6], o[7]);
    }
}

// ---------------------------------------------------------------------------
// Fused res + skip 1x1 convs: C[768,N] = RS[768,512] @ a, then
// rows <512: x += C + res_b ; rows >=512: skip += C + skip_b.
// ---------------------------------------------------------------------------
__global__ __launch_bounds__(256) void res_skip_k(
        const float* __restrict__ res_b, const float* __restrict__ skip_b,
        int layer) {
    __shared__ __align__(16) float Ws[16][128];
    __shared__ __align__(16) float Xs[16][128];
    const int tid = threadIdx.x, tx = tid & 15, ty = tid >> 4;
    const int t0 = blockIdx.x * 128, b = blockIdx.y, m0 = blockIdx.z * 128;
    const float* __restrict__ wl = g_RSp + (size_t)layer * (512 * 768);
    const float* __restrict__ ain = g_a + (size_t)b * (RC * T_LEN);

    unsigned long long acc[8][4];
    #pragma unroll
    for (int i = 0; i < 8; i++)
        #pragma unroll
        for (int j = 0; j < 4; j++) acc[i][j] = 0ull;

    float pw[8], px[8];
    #pragma unroll
    for (int l = 0; l < 8; l++) {
        int idx = tid + l * 256, r = idx >> 7, m = idx & 127;
        pw[l] = wl[r * 768 + m0 + m];
        px[l] = ain[r * T_LEN + t0 + m];
    }
    for (int it = 0; it < 32; ++it) {
        #pragma unroll
        for (int l = 0; l < 8; l++) {
            int idx = tid + l * 256, r = idx >> 7, m = idx & 127;
            Ws[r][m] = pw[l];
            Xs[r][m] = px[l];
        }
        __syncthreads();
        if (it + 1 < 32) {
            int kc = (it + 1) * 16;
            #pragma unroll
            for (int l = 0; l < 8; l++) {
                int idx = tid + l * 256, r = idx >> 7, m = idx & 127;
                pw[l] = wl[(kc + r) * 768 + m0 + m];
                px[l] = ain[(kc + r) * T_LEN + t0 + m];
            }
        }
        #pragma unroll
        for (int k = 0; k < 16; k++) {
            const float4 wa = *(const float4*)&Ws[k][ty * 4];
            const float4 wb = *(const float4*)&Ws[k][64 + ty * 4];
            const ulonglong2 xA = *(const ulonglong2*)&Xs[k][tx * 4];
            const ulonglong2 xB = *(const ulonglong2*)&Xs[k][64 + tx * 4];
            unsigned long long xf[4] = {xA.x, xA.y, xB.x, xB.y};
            float wv[8] = {wa.x, wa.y, wa.z, wa.w, wb.x, wb.y, wb.z, wb.w};
            #pragma unroll
            for (int i = 0; i < 8; i++) {
                unsigned long long wp = pack2(wv[i]);
                #pragma unroll
                for (int j = 0; j < 4; j++) ffma2(acc[i][j], wp, xf[j]);
            }
        }
        __syncthreads();
    }
    #pragma unroll
    for (int i = 0; i < 8; i++) {
        int ml = (i < 4) ? (ty * 4 + i) : (64 + ty * 4 + (i - 4));
        int m = m0 + ml;
        float bias; float* ptr;
        if (m < 512) {
            bias = res_b[layer * 512 + m];
            ptr = g_x + ((size_t)(b * 512 + m)) * T_LEN + t0;
        } else {
            bias = skip_b[layer * 256 + (m - 512)];
            ptr = g_skip + ((size_t)(b * 256 + (m - 512))) * T_LEN + t0;
        }
        float4 v = *(float4*)&ptr[tx * 4];
        v.x += lo2(acc[i][0]) + bias; v.y += hi2(acc[i][0]) + bias;
        v.z += lo2(acc[i][1]) + bias; v.w += hi2(acc[i][1]) + bias;
        *(float4*)&ptr[tx * 4] = v;
        float4 u = *(float4*)&ptr[64 + tx * 4];
        u.x += lo2(acc[i][2]) + bias; u.y += hi2(acc[i][2]) + bias;
        u.z += lo2(acc[i][3]) + bias; u.w += hi2(acc[i][3]) + bias;
        *(float4*)&ptr[64 + tx * 4] = u;
    }
}

// ---- fc1: y = relu(fc1_w @ skip + b) --------------------------------------
__global__ __launch_bounds__(256) void fc1_gemm_k(const float* __restrict__ fc1_b) {
    __shared__ __align__(16) float Ws[16][128];
    __shared__ __align__(16) float Xs[16][128];
    const int tid = threadIdx.x, tx = tid & 15, ty = tid >> 4;
    const int t0 = blockIdx.x * 128, b = blockIdx.y, m0 = blockIdx.z * 128;
    const float* __restrict__ sin_ = g_skip + (size_t)b * (SC * T_LEN);

    unsigned long long acc[8][4];
    #pragma unroll
    for (int i = 0; i < 8; i++)
        #pragma unroll
        for (int j = 0; j < 4; j++) acc[i][j] = 0ull;

    float pw[8], px[8];
    #pragma unroll
    for (int l = 0; l < 8; l++) {
        int idx = tid + l * 256, r = idx >> 7, m = idx & 127;
        pw[l] = g_F1p[r * 256 + m0 + m];
        px[l] = sin_[r * T_LEN + t0 + m];
    }
    for (int it = 0; it < 16; ++it) {
        #pragma unroll
        for (int l = 0; l < 8; l++) {
            int idx = tid + l * 256, r = idx >> 7, m = idx & 127;
            Ws[r][m] = pw[l];
            Xs[r][m] = px[l];
        }
        __syncthreads();
        if (it + 1 < 16) {
            int kc = (it + 1) * 16;
            #pragma unroll
            for (int l = 0; l < 8; l++) {
                int idx = tid + l * 256, r = idx >> 7, m = idx & 127;
                pw[l] = g_F1p[(kc + r) * 256 + m0 + m];
                px[l] = sin_[(kc + r) * T_LEN + t0 + m];
            }
        }
        #pragma unroll
        for (int k = 0; k < 16; k++) {
            const float4 wa = *(const float4*)&Ws[k][ty * 4];
            const float4 wb = *(const float4*)&Ws[k][64 + ty * 4];
            const ulonglong2 xA = *(const ulonglong2*)&Xs[k][tx * 4];
            const ulonglong2 xB = *(const ulonglong2*)&Xs[k][64 + tx * 4];
            unsigned long long xf[4] = {xA.x, xA.y, xB.x, xB.y};
            float wv[8] = {wa.x, wa.y, wa.z, wa.w, wb.x, wb.y, wb.z, wb.w};
            #pragma unroll
            for (int i = 0; i < 8; i++) {
                unsigned long long wp = pack2(wv[i]);
                #pragma unroll
                for (int j = 0; j < 4; j++) ffma2(acc[i][j], wp, xf[j]);
            }
        }
        __syncthreads();
    }
    #pragma unroll
    for (int i = 0; i < 8; i++) {
        int ml = (i < 4) ? (ty * 4 + i) : (64 + ty * 4 + (i - 4));
        int m = m0 + ml;
        float bias = fc1_b[m];
        float* ptr = g_y + ((size_t)(b * 256 + m)) * T_LEN + t0;
        float4 v;
        v.x = fmaxf(lo2(acc[i][0]) + bias, 0.f);
        v.y = fmaxf(hi2(acc[i][0]) + bias, 0.f);
        v.z = fmaxf(lo2(acc[i][1]) + bias, 0.f);
        v.w = fmaxf(hi2(acc[i][1]) + bias, 0.f);
        *(float4*)&ptr[tx * 4] = v;
        float4 u;
        u.x = fmaxf(lo2(acc[i][2]) + bias, 0.f);
        u.y = fmaxf(hi2(acc[i][2]) + bias, 0.f);
        u.z = fmaxf(lo2(acc[i][3]) + bias, 0.f);
        u.w = fmaxf(hi2(acc[i][3]) + bias, 0.f);
        *(float4*)&ptr[64 + tx * 4] = u;
    }
}

// ---- fc2: out = tanh(fc2_w . y + b) ---------------------------------------
__global__ void fc2_k(const float* __restrict__ fc2_w,
                      const float* __restrict__ fc2_b,
                      float* __restrict__ out) {
    int b = blockIdx.y;
    int t = blockIdx.x * 256 + threadIdx.x;
    const float* yb = g_y + (size_t)b * (SC * T_LEN) + t;
    float s = fc2_b[0];
    #pragma unroll 8
    for (int c = 0; c < SC; c++) s += fc2_w[c] * yb[(size_t)c * T_LEN];
    out[b * T_LEN + t] = tanhf(s);
}

// ---------------------------------------------------------------------------
extern "C" void kernel_launch(void* const* d_in, const int* in_sizes, int n_in,
                              void* d_out, int out_size) {
    (void)in_sizes; (void)n_in; (void)out_size;
    const float* mel     = (const float*)d_in[0];
    const float* audio   = (const float*)d_in[1];
    const float* start_w = (const float*)d_in[2];
    const float* start_b = (const float*)d_in[3];
    const float* mel_w   = (const float*)d_in[4];
    const float* mel_b   = (const float*)d_in[5];
    const float* dil_w   = (const float*)d_in[6];
    const float* dil_b   = (const float*)d_in[7];
    const float* res_w   = (const float*)d_in[8];
    const float* res_b   = (const float*)d_in[9];
    const float* skip_w  = (const float*)d_in[10];
    const float* skip_b  = (const float*)d_in[11];
    const float* fc1_w   = (const float*)d_in[12];
    const float* fc1_b   = (const float*)d_in[13];
    const float* fc2_w   = (const float*)d_in[14];
    const float* fc2_b   = (const float*)d_in[15];
    float* out = (float*)d_out;

    prep_dil_k<<<184320, 256>>>(dil_w);               // 30*3*512*1024 / 256
    prep_rs_k <<<46080, 256>>>(res_w, skip_w);        // 30*512*768 / 256
    prep_fc1_k<<<256, 256>>>(fc1_w);
    init_x_k<<<dim3(64, 2, 8), 256>>>(mel, audio, start_w, start_b, mel_w, mel_b);
    zero_skip_k<<<16384, 256>>>();

    for (int l = 0; l < NL; l++) {
        int d = 1 << (l % 10);
        dil_gate_k<<<dim3(64, 2, 8), 256>>>(dil_b, l, d);
        res_skip_k<<<dim3(64, 2, 6), 256>>>(res_b, skip_b, l);
    }
    fc1_gemm_k<<<dim3(64, 2, 2), 256>>>(fc1_b);
    fc2_k<<<dim3(32, 2), 256>>>(fc2_w, fc2_b, out);
}

// round 3
// speedup vs baseline: 2.0745x; 2.0745x over previous
#include <cuda_runtime.h>
#include <cuda_bf16.h>
#include <cstdint>

// ---------------------------------------------------------------------------
// WaveNet vocoder via mma.sync bf16 (hi/lo split, 3 passes) — sm_103-safe PTX.
// B=2, T=8192, RES_C=512, SKIP_C=256, K=3, 30 layers.
// Activations time-major [t][512] bf16 hi/lo planes.
// ---------------------------------------------------------------------------

#define T_LEN 8192
#define NB    2
#define RC    512
#define SC    256
#define NL    30

// smem geometry: rows padded to 72 bf16 (144 B) for conflict-free ldmatrix
#define SROW   144
#define APLANE 18432            // 128 rows * 144 B
#define STAGE  73728            // Ah | Al | Bh | Bl
#define DSMB   147456           // 2 stages

// ---- global scratch --------------------------------------------------------
__device__ __nv_bfloat16 g_Wd [(size_t)NL*3*2*1024*512]; // [l][tap][pl][cop][ci]
__device__ __nv_bfloat16 g_Wrs[(size_t)NL*2*768*512];    // [l][pl][m][ci]
__device__ __nv_bfloat16 g_xh[(size_t)NB*T_LEN*RC], g_xl[(size_t)NB*T_LEN*RC];
__device__ __nv_bfloat16 g_ah[(size_t)NB*T_LEN*RC], g_al[(size_t)NB*T_LEN*RC];
__device__ float g_skip[(size_t)NB*SC*T_LEN];            // [b][c][t]
__device__ float g_y   [(size_t)NB*SC*T_LEN];            // [b][c][t]
__device__ float g_F1p [SC*SC];                          // [ci][co]

// ---- PTX helpers -----------------------------------------------------------
__device__ __forceinline__ uint32_t smem_u32(const void* p) {
    uint32_t a;
    asm("{ .reg .u64 t; cvta.to.shared.u64 t, %1; cvt.u32.u64 %0, t; }"
        : "=r"(a) : "l"(p));
    return a;
}
__device__ __forceinline__ void cp16(uint32_t dst, const void* src) {
    asm volatile("cp.async.ca.shared.global [%0], [%1], 16;"
                 :: "r"(dst), "l"(src));
}
__device__ __forceinline__ void cp16z(uint32_t dst, const void* src, int ok) {
    int sz = ok ? 16 : 0;
    asm volatile("cp.async.ca.shared.global [%0], [%1], 16, %2;"
                 :: "r"(dst), "l"(src), "r"(sz));
}
#define CP_COMMIT() asm volatile("cp.async.commit_group;" ::: "memory")
#define CP_WAIT1()  asm volatile("cp.async.wait_group 1;" ::: "memory")
#define CP_WAIT0()  asm volatile("cp.async.wait_group 0;" ::: "memory")

__device__ __forceinline__ void ldsm4(uint32_t* r, uint32_t a) {
    asm volatile("ldmatrix.sync.aligned.m8n8.x4.shared.b16 {%0,%1,%2,%3}, [%4];"
                 : "=r"(r[0]), "=r"(r[1]), "=r"(r[2]), "=r"(r[3]) : "r"(a));
}
__device__ __forceinline__ void mma16816(float* c, const uint32_t* a,
                                         uint32_t b0, uint32_t b1) {
    asm volatile(
        "mma.sync.aligned.m16n8k16.row.col.f32.bf16.bf16.f32 "
        "{%0,%1,%2,%3},{%4,%5,%6,%7},{%8,%9},{%0,%1,%2,%3};"
        : "+f"(c[0]), "+f"(c[1]), "+f"(c[2]), "+f"(c[3])
        : "r"(a[0]), "r"(a[1]), "r"(a[2]), "r"(a[3]), "r"(b0), "r"(b1));
}

__device__ __forceinline__ float gatefn(float f, float g) {
    float ef = __expf(2.f * f);
    float th = 1.f - __fdividef(2.f, ef + 1.f);
    float sg = __fdividef(1.f, 1.f + __expf(-g));
    return th * sg;
}
__device__ __forceinline__ void split_store(__nv_bfloat16* ph, __nv_bfloat16* pl,
                                            size_t o, float v) {
    __nv_bfloat16 h = __float2bfloat16(v);
    ph[o] = h;
    pl[o] = __float2bfloat16(v - __bfloat162float(h));
}

// ---- one K-chunk (64 ci) of hi/lo 3-pass MMA ------------------------------
// aB: smem addr of Ah plane base; bB: smem addr of Bh plane base.
// Warp computes rows [wm*32,+32), cols [wn*64,+64).
__device__ __forceinline__ void chunk_mma(float acc[2][8][4], uint32_t aB,
                                          uint32_t bB, int wm, int wn,
                                          uint32_t laneOff) {
    #pragma unroll
    for (int ks = 0; ks < 4; ks++) {
        uint32_t aH[2][4], aL[2][4], bH[4][4], bL[4][4];
        #pragma unroll
        for (int mi = 0; mi < 2; mi++) {
            uint32_t ra = aB + (wm * 32 + mi * 16) * SROW + ks * 32 + laneOff;
            ldsm4(aH[mi], ra);
            ldsm4(aL[mi], ra + APLANE);
        }
        #pragma unroll
        for (int np = 0; np < 4; np++) {
            uint32_t rb = bB + (wn * 64 + np * 16) * SROW + ks * 32 + laneOff;
            ldsm4(bH[np], rb);
            ldsm4(bL[np], rb + APLANE);
        }
        #pragma unroll
        for (int mi = 0; mi < 2; mi++)
            #pragma unroll
            for (int np = 0; np < 4; np++) {
                mma16816(acc[mi][2 * np],     aH[mi], bH[np][0], bH[np][2]);
                mma16816(acc[mi][2 * np + 1], aH[mi], bH[np][1], bH[np][3]);
                mma16816(acc[mi][2 * np],     aH[mi], bL[np][0], bL[np][2]);
                mma16816(acc[mi][2 * np + 1], aH[mi], bL[np][1], bL[np][3]);
                mma16816(acc[mi][2 * np],     aL[mi], bH[np][0], bH[np][2]);
                mma16816(acc[mi][2 * np + 1], aL[mi], bH[np][1], bH[np][3]);
            }
    }
}

// Store warp accumulators to f32 smem tile [128][132].
__device__ __forceinline__ void acc_to_smem(float* sE, float acc[2][8][4],
                                            int wm, int wn, int lane) {
    int r0 = wm * 32 + (lane >> 2);
    int cb = wn * 64 + (lane & 3) * 2;
    #pragma unroll
    for (int mi = 0; mi < 2; mi++)
        #pragma unroll
        for (int ni = 0; ni < 8; ni++) {
            int rr = r0 + mi * 16, cc = cb + ni * 8;
            sE[rr * 132 + cc]           = acc[mi][ni][0];
            sE[rr * 132 + cc + 1]       = acc[mi][ni][1];
            sE[(rr + 8) * 132 + cc]     = acc[mi][ni][2];
            sE[(rr + 8) * 132 + cc + 1] = acc[mi][ni][3];
        }
}

// ---- weight prep -----------------------------------------------------------
__global__ void prep_dil_k(const float* __restrict__ dil_w) {
    int idx = blockIdx.x * 256 + threadIdx.x;   // 47,185,920
    int ci = idx & 511;
    int r = idx >> 9;
    int co = r & 1023; r >>= 10;
    int tap = r % 3, l = r / 3;
    float w = dil_w[((size_t)(l * 1024 + co) * 512 + ci) * 3 + tap];
    int cop;
    if (co < 512) cop = (co >> 6) * 128 + (co & 63);
    else { int c = co - 512; cop = (c >> 6) * 128 + 64 + (c & 63); }
    __nv_bfloat16 h = __float2bfloat16(w);
    __nv_bfloat16 lo = __float2bfloat16(w - __bfloat162float(h));
    size_t base = ((size_t)(l * 3 + tap) * 2) * 1024 * 512 + (size_t)cop * 512 + ci;
    g_Wd[base] = h;
    g_Wd[base + (size_t)1024 * 512] = lo;
}

__global__ void prep_rs_k(const float* __restrict__ res_w,
                          const float* __restrict__ skip_w) {
    int idx = blockIdx.x * 256 + threadIdx.x;   // 11,796,480
    int ci = idx & 511;
    int r = idx >> 9;
    int m = r % 768, l = r / 768;
    float w = (m < 512) ? res_w[((size_t)(l * 512 + m)) * 512 + ci]
                        : skip_w[((size_t)(l * 256 + m - 512)) * 512 + ci];
    __nv_bfloat16 h = __float2bfloat16(w);
    __nv_bfloat16 lo = __float2bfloat16(w - __bfloat162float(h));
    size_t base = ((size_t)(l * 2) * 768 + m) * 512 + ci;
    g_Wrs[base] = h;
    g_Wrs[base + (size_t)768 * 512] = lo;
}

__global__ void prep_fc1_k(const float* __restrict__ fc1_w) {
    int idx = blockIdx.x * 256 + threadIdx.x;
    int co = idx & 255, ci = idx >> 8;
    g_F1p[ci * 256 + co] = fc1_w[co * 256 + ci];
}

__global__ void zero_skip_k() {
    g_skip[(size_t)blockIdx.x * 256 + threadIdx.x] = 0.f;
}

// ---- init: x[t][c] = start_w*audio + mel 1x1 + biases (hi/lo split) --------
__global__ __launch_bounds__(256) void init_x_k(
        const float* __restrict__ mel, const float* __restrict__ audio,
        const float* __restrict__ start_w, const float* __restrict__ start_b,
        const float* __restrict__ mel_w, const float* __restrict__ mel_b) {
    extern __shared__ float ism[];
    float* wsm  = ism;                 // [64][81]
    float* mels = ism + 64 * 81;       // [80][129]
    __shared__ float auds[128];
    const int tid = threadIdx.x;
    const int t0 = blockIdx.x * 128, b = blockIdx.y, cb = blockIdx.z * 64;
    for (int i = tid; i < 64 * 80; i += 256) {
        int c = i / 80, m = i % 80;
        wsm[c * 81 + m] = mel_w[(size_t)(cb + c) * 80 + m];
    }
    for (int i = tid; i < 80 * 128; i += 256) {
        int m = i >> 7, t = i & 127;
        mels[m * 129 + t] = mel[((size_t)(b * 80 + m)) * T_LEN + t0 + t];
    }
    if (tid < 128) auds[tid] = audio[(size_t)b * T_LEN + t0 + tid];
    __syncthreads();
    const int c_l = tid & 63, tg = tid >> 6;
    const int c = cb + c_l;
    const float sw = start_w[c], bb = start_b[c] + mel_b[c];
    for (int ti = 0; ti < 32; ti++) {
        int t = tg * 32 + ti;
        float acc = bb + sw * auds[t];
        #pragma unroll 8
        for (int m = 0; m < 80; m++) acc += wsm[c_l * 81 + m] * mels[m * 129 + t];
        split_store(g_xh, g_xl, ((size_t)b * T_LEN + t0 + t) * RC + c, acc);
    }
}

// ---- dilated conv + gate ---------------------------------------------------
__device__ __forceinline__ void dil_load_chunk(char* /*unused*/, uint32_t sb,
        int layer, int tap, int ci0, int t0, int b, int mt, int dil, int tid) {
    const __nv_bfloat16* wl = g_Wd + ((size_t)(layer * 3 + tap) * 2) * 1024 * 512;
    #pragma unroll
    for (int p = 0; p < 8; p++) {                       // A: 2048 16B chunks
        int idx = tid + p * 256;
        int pl = idx >> 10, rem = idx & 1023, r = rem >> 3, j = rem & 7;
        const __nv_bfloat16* src = wl + ((size_t)pl * 1024 + mt * 128 + r) * 512
                                      + ci0 + j * 8;
        cp16(sb + pl * APLANE + r * SROW + j * 16, src);
    }
    int shift = (tap - 1) * dil;
    #pragma unroll
    for (int p = 0; p < 8; p++) {                       // B: 2048 16B chunks
        int idx = tid + p * 256;
        int pl = idx >> 10, rem = idx & 1023, r = rem >> 3, j = rem & 7;
        int t = t0 + r + shift;
        int ok = (t >= 0 && t < T_LEN);
        const __nv_bfloat16* plane = pl ? g_al : g_ah;  // placeholder; fixed below
        plane = pl ? g_xl : g_xh;
        const __nv_bfloat16* src = plane + ((size_t)b * T_LEN + (ok ? t : 0)) * RC
                                        + ci0 + j * 8;
        cp16z(sb + 2 * APLANE + pl * APLANE + r * SROW + j * 16, src, ok);
    }
}

__global__ __launch_bounds__(256) void dil_mma_k(
        const float* __restrict__ dil_b, int layer, int dil) {
    extern __shared__ char dsm[];
    const int tid = threadIdx.x, wid = tid >> 5, lane = tid & 31;
    const int wm = wid & 3, wn = wid >> 2;
    const int mt = blockIdx.z, b = blockIdx.y, t0 = blockIdx.x * 128;
    const uint32_t dsm0 = smem_u32(dsm);
    const uint32_t laneOff = (lane & 15) * SROW + (lane >> 4) * 16;

    float acc[2][8][4];
    #pragma unroll
    for (int i = 0; i < 2; i++)
        #pragma unroll
        for (int j = 0; j < 8; j++)
            #pragma unroll
            for (int k = 0; k < 4; k++) acc[i][j][k] = 0.f;

    dil_load_chunk(dsm, dsm0, layer, 0, 0, t0, b, mt, dil, tid);
    CP_COMMIT();
    for (int it = 0; it < 24; it++) {
        if (it + 1 < 24) {
            int tap = (it + 1) >> 3, ci0 = ((it + 1) & 7) * 64;
            dil_load_chunk(dsm, dsm0 + ((it + 1) & 1) * STAGE,
                           layer, tap, ci0, t0, b, mt, dil, tid);
            CP_COMMIT();
            CP_WAIT1();
        } else {
            CP_WAIT0();
        }
        __syncthreads();
        uint32_t aB = dsm0 + (it & 1) * STAGE;
        chunk_mma(acc, aB, aB + 2 * APLANE, wm, wn, laneOff);
        __syncthreads();
    }

    float* sE = (float*)dsm;
    acc_to_smem(sE, acc, wm, wn, lane);
    __syncthreads();

    const int c_l = tid & 63, tg = tid >> 6;
    const float bf = dil_b[layer * 1024 + mt * 64 + c_l];
    const float bg = dil_b[layer * 1024 + 512 + mt * 64 + c_l];
    const size_t rb = (size_t)b * T_LEN + t0;
    for (int ti = 0; ti < 32; ti++) {
        int t = tg * 32 + ti;
        float f = sE[c_l * 132 + t] + bf;
        float g = sE[(64 + c_l) * 132 + t] + bg;
        split_store(g_ah, g_al, (rb + t) * RC + mt * 64 + c_l, gatefn(f, g));
    }
}

// ---- fused res + skip ------------------------------------------------------
__global__ __launch_bounds__(256) void res_mma_k(
        const float* __restrict__ res_b, const float* __restrict__ skip_b,
        int layer) {
    extern __shared__ char dsm[];
    const int tid = threadIdx.x, wid = tid >> 5, lane = tid & 31;
    const int wm = wid & 3, wn = wid >> 2;
    const int m0 = blockIdx.z * 128, b = blockIdx.y, t0 = blockIdx.x * 128;
    const uint32_t dsm0 = smem_u32(dsm);
    const uint32_t laneOff = (lane & 15) * SROW + (lane >> 4) * 16;

    float acc[2][8][4];
    #pragma unroll
    for (int i = 0; i < 2; i++)
        #pragma unroll
        for (int j = 0; j < 8; j++)
            #pragma unroll
            for (int k = 0; k < 4; k++) acc[i][j][k] = 0.f;

    const __nv_bfloat16* wl = g_Wrs + (size_t)(layer * 2) * 768 * 512;

    auto load_chunk = [&](uint32_t sb, int ci0) {
        #pragma unroll
        for (int p = 0; p < 8; p++) {
            int idx = tid + p * 256;
            int pl = idx >> 10, rem = idx & 1023, r = rem >> 3, j = rem & 7;
            const __nv_bfloat16* src = wl + ((size_t)pl * 768 + m0 + r) * 512
                                          + ci0 + j * 8;
            cp16(sb + pl * APLANE + r * SROW + j * 16, src);
        }
        #pragma unroll
        for (int p = 0; p < 8; p++) {
            int idx = tid + p * 256;
            int pl = idx >> 10, rem = idx & 1023, r = rem >> 3, j = rem & 7;
            const __nv_bfloat16* plane = pl ? g_al : g_ah;
            const __nv_bfloat16* src = plane + ((size_t)b * T_LEN + t0 + r) * RC
                                            + ci0 + j * 8;
            cp16(sb + 2 * APLANE + pl * APLANE + r * SROW + j * 16, src);
        }
    };

    load_chunk(dsm0, 0);
    CP_COMMIT();
    for (int it = 0; it < 8; it++) {
        if (it + 1 < 8) {
            load_chunk(dsm0 + ((it + 1) & 1) * STAGE, (it + 1) * 64);
            CP_COMMIT();
            CP_WAIT1();
        } else {
            CP_WAIT0();
        }
        __syncthreads();
        uint32_t aB = dsm0 + (it & 1) * STAGE;
        chunk_mma(acc, aB, aB + 2 * APLANE, wm, wn, laneOff);
        __syncthreads();
    }

    float* sE = (float*)dsm;
    acc_to_smem(sE, acc, wm, wn, lane);
    __syncthreads();

    if (m0 < 512) {             // residual: x += d + bias (re-split hi/lo)
        const int c_l = tid & 127, tg = tid >> 7;
        const float rb = res_b[layer * 512 + m0 + c_l];
        for (int ti = 0; ti < 64; ti++) {
            int t = tg * 64 + ti;
            float d = sE[c_l * 132 + t] + rb;
            size_t o = ((size_t)b * T_LEN + t0 + t) * RC + m0 + c_l;
            float nx = __bfloat162float(g_xh[o]) + __bfloat162float(g_xl[o]) + d;
            split_store(g_xh, g_xl, o, nx);
        }
    } else {                    // skip accumulation (fp32, [b][c][t])
        const int t_l = tid & 127, cg = tid >> 7;
        for (int c = cg * 64; c < cg * 64 + 64; c++) {
            float sb2 = skip_b[layer * 256 + (m0 - 512) + c];
            float* dst = g_skip + ((size_t)b * 256 + (m0 - 512) + c) * T_LEN + t0;
            dst[t_l] += sE[c * 132 + t_l] + sb2;
        }
    }
}

// ---- fc1 (fp32 FFMA2 GEMM) -------------------------------------------------
__device__ __forceinline__ void ffma2(unsigned long long& d, unsigned long long a,
                                      unsigned long long b) {
    asm("fma.rn.f32x2 %0, %1, %2, %0;" : "+l"(d) : "l"(a), "l"(b));
}
__device__ __forceinline__ unsigned long long pack2(float v) {
    unsigned long long r; unsigned u = __float_as_uint(v);
    asm("mov.b64 %0, {%1, %1};" : "=l"(r) : "r"(u));
    return r;
}
__device__ __forceinline__ float lo2(unsigned long long v) {
    return __uint_as_float((unsigned)v);
}
__device__ __forceinline__ float hi2(unsigned long long v) {
    return __uint_as_float((unsigned)(v >> 32));
}

__global__ __launch_bounds__(256) void fc1_gemm_k(const float* __restrict__ fc1_b) {
    __shared__ __align__(16) float Ws[16][128];
    __shared__ __align__(16) float Xs[16][128];
    const int tid = threadIdx.x, tx = tid & 15, ty = tid >> 4;
    const int t0 = blockIdx.x * 128, b = blockIdx.y, m0 = blockIdx.z * 128;
    const float* __restrict__ sin_ = g_skip + (size_t)b * (SC * T_LEN);

    unsigned long long acc[8][4];
    #pragma unroll
    for (int i = 0; i < 8; i++)
        #pragma unroll
        for (int j = 0; j < 4; j++) acc[i][j] = 0ull;

    float pw[8], px[8];
    #pragma unroll
    for (int l = 0; l < 8; l++) {
        int idx = tid + l * 256, r = idx >> 7, m = idx & 127;
        pw[l] = g_F1p[r * 256 + m0 + m];
        px[l] = sin_[r * T_LEN + t0 + m];
    }
    for (int it = 0; it < 16; ++it) {
        #pragma unroll
        for (int l = 0; l < 8; l++) {
            int idx = tid + l * 256, r = idx >> 7, m = idx & 127;
            Ws[r][m] = pw[l];
            Xs[r][m] = px[l];
        }
        __syncthreads();
        if (it + 1 < 16) {
            int kc = (it + 1) * 16;
            #pragma unroll
            for (int l = 0; l < 8; l++) {
                int idx = tid + l * 256, r = idx >> 7, m = idx & 127;
                pw[l] = g_F1p[(kc + r) * 256 + m0 + m];
                px[l] = sin_[(kc + r) * T_LEN + t0 + m];
            }
        }
        #pragma unroll
        for (int k = 0; k < 16; k++) {
            const float4 wa = *(const float4*)&Ws[k][ty * 4];
            const float4 wb = *(const float4*)&Ws[k][64 + ty * 4];
            const ulonglong2 xA = *(const ulonglong2*)&Xs[k][tx * 4];
            const ulonglong2 xB = *(const ulonglong2*)&Xs[k][64 + tx * 4];
            unsigned long long xf[4] = {xA.x, xA.y, xB.x, xB.y};
            float wv[8] = {wa.x, wa.y, wa.z, wa.w, wb.x, wb.y, wb.z, wb.w};
            #pragma unroll
            for (int i = 0; i < 8; i++) {
                unsigned long long wp = pack2(wv[i]);
                #pragma unroll
                for (int j = 0; j < 4; j++) ffma2(acc[i][j], wp, xf[j]);
            }
        }
        __syncthreads();
    }
    #pragma unroll
    for (int i = 0; i < 8; i++) {
        int ml = (i < 4) ? (ty * 4 + i) : (64 + ty * 4 + (i - 4));
        int m = m0 + ml;
        float bias = fc1_b[m];
        float* ptr = g_y + ((size_t)(b * 256 + m)) * T_LEN + t0;
        float4 v;
        v.x = fmaxf(lo2(acc[i][0]) + bias, 0.f);
        v.y = fmaxf(hi2(acc[i][0]) + bias, 0.f);
        v.z = fmaxf(lo2(acc[i][1]) + bias, 0.f);
        v.w = fmaxf(hi2(acc[i][1]) + bias, 0.f);
        *(float4*)&ptr[tx * 4] = v;
        float4 u;
        u.x = fmaxf(lo2(acc[i][2]) + bias, 0.f);
        u.y = fmaxf(hi2(acc[i][2]) + bias, 0.f);
        u.z = fmaxf(lo2(acc[i][3]) + bias, 0.f);
        u.w = fmaxf(hi2(acc[i][3]) + bias, 0.f);
        *(float4*)&ptr[64 + tx * 4] = u;
    }
}

__global__ void fc2_k(const float* __restrict__ fc2_w,
                      const float* __restrict__ fc2_b,
                      float* __restrict__ out) {
    int b = blockIdx.y;
    int t = blockIdx.x * 256 + threadIdx.x;
    const float* yb = g_y + (size_t)b * (SC * T_LEN) + t;
    float s = fc2_b[0];
    #pragma unroll 8
    for (int c = 0; c < SC; c++) s += fc2_w[c] * yb[(size_t)c * T_LEN];
    out[b * T_LEN + t] = tanhf(s);
}

// ---------------------------------------------------------------------------
extern "C" void kernel_launch(void* const* d_in, const int* in_sizes, int n_in,
                              void* d_out, int out_size) {
    (void)in_sizes; (void)n_in; (void)out_size;
    const float* mel     = (const float*)d_in[0];
    const float* audio   = (const float*)d_in[1];
    const float* start_w = (const float*)d_in[2];
    const float* start_b = (const float*)d_in[3];
    const float* mel_w   = (const float*)d_in[4];
    const float* mel_b   = (const float*)d_in[5];
    const float* dil_w   = (const float*)d_in[6];
    const float* dil_b   = (const float*)d_in[7];
    const float* res_w   = (const float*)d_in[8];
    const float* res_b   = (const float*)d_in[9];
    const float* skip_w  = (const float*)d_in[10];
    const float* skip_b  = (const float*)d_in[11];
    const float* fc1_w   = (const float*)d_in[12];
    const float* fc1_b   = (const float*)d_in[13];
    const float* fc2_w   = (const float*)d_in[14];
    const float* fc2_b   = (const float*)d_in[15];
    float* out = (float*)d_out;

    static int s_attr_done = 0;
    if (!s_attr_done) {
        cudaFuncSetAttribute(dil_mma_k, cudaFuncAttributeMaxDynamicSharedMemorySize, DSMB);
        cudaFuncSetAttribute(res_mma_k, cudaFuncAttributeMaxDynamicSharedMemorySize, DSMB);
        cudaFuncSetAttribute(init_x_k, cudaFuncAttributeMaxDynamicSharedMemorySize, 65536);
        s_attr_done = 1;
    }

    prep_dil_k<<<184320, 256>>>(dil_w);
    prep_rs_k <<<46080, 256>>>(res_w, skip_w);
    prep_fc1_k<<<256, 256>>>(fc1_w);
    init_x_k<<<dim3(64, 2, 8), 256, (64 * 81 + 80 * 129) * 4>>>(
        mel, audio, start_w, start_b, mel_w, mel_b);
    zero_skip_k<<<16384, 256>>>();

    for (int l = 0; l < NL; l++) {
        int d = 1 << (l % 10);
        dil_mma_k<<<dim3(64, 2, 8), 256, DSMB>>>(dil_b, l, d);
        res_mma_k<<<dim3(64, 2, 6), 256, DSMB>>>(res_b, skip_b, l);
    }
    fc1_gemm_k<<<dim3(64, 2, 2), 256>>>(fc1_b);
    fc2_k<<<dim3(32, 2), 256>>>(fc2_w, fc2_b, out);
}